// round 14
// baseline (speedup 1.0000x reference)
#include <cuda_runtime.h>
#include <math.h>

// Scratch (no cudaMalloc allowed)
__device__ float g_feats[32 * 1280];   // [B, (K+1)*C] pooled means
__device__ float g_h[32 * 32];         // [MID][B] hidden after BN+ReLU (transposed)
__device__ float g_w1[32 * 256];       // [B, C] sigmoid self-gate
__device__ float g_w2[32 * 4 * 256];   // [B, K, C] softmax branch gates

#define B_ 32
#define C_ 256
#define K_ 4
#define HW_ 1024
#define MID_ 32
#define FEAT_ 1280   // (K+1)*C
#define HALFROWS_ 20480   // 40960 rows / 2

// ---------------- Kernel 1: global average pool, 2 far-split rows per warp --------
// Warp w handles rows w and w+20480. Uniform switch per row (no pointer array),
// interleaved loads -> 16 LDG.128 in flight per warp.
__global__ void k_means(const float* __restrict__ y,
                        const float* __restrict__ x0,
                        const float* __restrict__ x1,
                        const float* __restrict__ x2,
                        const float* __restrict__ x3) {
    int warp = (blockIdx.x * blockDim.x + threadIdx.x) >> 5;
    int lane = threadIdx.x & 31;

    int rA = warp;                 // row A
    int rB = warp + HALFROWS_;     // row B

    int bA = rA / FEAT_;
    int jA = rA - bA * FEAT_;
    int slotA = jA >> 8, cA = jA & 255;
    const float* baseA;
    switch (slotA) {
        case 0: baseA = y;  break;
        case 1: baseA = x0; break;
        case 2: baseA = x1; break;
        case 3: baseA = x2; break;
        default: baseA = x3; break;
    }

    int bB = rB / FEAT_;
    int jB = rB - bB * FEAT_;
    int slotB = jB >> 8, cB = jB & 255;
    const float* baseB;
    switch (slotB) {
        case 0: baseB = y;  break;
        case 1: baseB = x0; break;
        case 2: baseB = x1; break;
        case 3: baseB = x2; break;
        default: baseB = x3; break;
    }

    const float4* pA = reinterpret_cast<const float4*>(baseA + (size_t)(bA * C_ + cA) * HW_);
    const float4* pB = reinterpret_cast<const float4*>(baseB + (size_t)(bB * C_ + cB) * HW_);

    float sA = 0.f, sB = 0.f;
#pragma unroll
    for (int i = 0; i < 8; i++) {          // interleaved: 16 loads in flight
        float4 va = pA[lane + i * 32];
        float4 vb = pB[lane + i * 32];
        sA += (va.x + va.y) + (va.z + va.w);
        sB += (vb.x + vb.y) + (vb.z + vb.w);
    }
#pragma unroll
    for (int o = 16; o; o >>= 1) {
        sA += __shfl_xor_sync(0xffffffffu, sA, o);
        sB += __shfl_xor_sync(0xffffffffu, sB, o);
    }
    if (lane == 0) {
        g_feats[rA] = sA * (1.0f / 1024.0f);
        g_feats[rB] = sB * (1.0f / 1024.0f);
    }
}

// ---------------- Kernel 2a: GEMM1 + BN + ReLU, weight-coalesced (R9-proven) -------
__global__ void k_gate1(const float* __restrict__ conv1_w,   // [32,1280]
                        const float* __restrict__ bn_gamma,
                        const float* __restrict__ bn_beta,
                        const float* __restrict__ bn_mean,
                        const float* __restrict__ bn_var) {
    cudaTriggerProgrammaticLaunchCompletion();

    int m = blockIdx.x;
    int t = threadIdx.x;
    __shared__ float sw[FEAT_];

    for (int i = t; i < FEAT_; i += 256) sw[i] = conv1_w[m * FEAT_ + i];
    float mean = bn_mean[m];
    float scale = bn_gamma[m] * rsqrtf(bn_var[m] + 1e-5f);
    float beta = bn_beta[m];

    cudaGridDependencySynchronize();
    __syncthreads();

    int w = t >> 5, lane = t & 31;
#pragma unroll
    for (int bb = 0; bb < 4; bb++) {
        int b = w * 4 + bb;
        const float* f = g_feats + b * FEAT_;
        float s = 0.f;
#pragma unroll
        for (int k = 0; k < FEAT_ / 32; k++)
            s = fmaf(f[lane + k * 32], sw[lane + k * 32], s);
#pragma unroll
        for (int o = 16; o; o >>= 1) s += __shfl_xor_sync(0xffffffffu, s, o);
        if (lane == 0)
            g_h[m * B_ + b] = fmaxf(fmaf(s - mean, scale, beta), 0.f);
    }
}

// ---------------- Kernel 2b: GEMM2 + activations, weight-coalesced (R9-proven) -----
__global__ void k_gate2(const float* __restrict__ conv2_w,   // [1280,32]
                        const float* __restrict__ conv2_b) { // [1280]
    cudaTriggerProgrammaticLaunchCompletion();

    int cg = blockIdx.x;        // channels [cg*8, cg*8+8)
    int t = threadIdx.x;        // 256
    int c_local = t & 7;
    int b = t >> 3;

    __shared__ float sh2[5 * 8 * 33];            // [slot][c_local][mid], padded
    __shared__ float shh[MID_ * B_];             // [mid][b]

#pragma unroll
    for (int slot = 0; slot < 5; slot++) {
        int row = t >> 5, mid = t & 31;
        sh2[(slot * 8 + row) * 33 + mid] = conv2_w[(slot * 256 + cg * 8) * 32 + t];
    }
    float bias[5];
#pragma unroll
    for (int slot = 0; slot < 5; slot++)
        bias[slot] = conv2_b[slot * 256 + cg * 8 + c_local];

    cudaGridDependencySynchronize();
    for (int i = t; i < MID_ * B_; i += 256) shh[i] = g_h[i];
    __syncthreads();

    int c = cg * 8 + c_local;
    float v[5];
#pragma unroll
    for (int slot = 0; slot < 5; slot++) {
        float s = bias[slot];
        const float* wp = &sh2[(slot * 8 + c_local) * 33];
#pragma unroll
        for (int mid = 0; mid < MID_; mid++)
            s = fmaf(shh[mid * B_ + b], wp[mid], s);
        v[slot] = s;
    }

    g_w1[b * C_ + c] = 1.0f / (1.0f + expf(-v[0]));
    float mx = fmaxf(fmaxf(v[1], v[2]), fmaxf(v[3], v[4]));
    float e1 = expf(v[1] - mx), e2 = expf(v[2] - mx);
    float e3 = expf(v[3] - mx), e4 = expf(v[4] - mx);
    float inv = 1.0f / (e1 + e2 + e3 + e4);
    int gb = b * K_ * C_ + c;
    g_w2[gb + 0 * C_] = e1 * inv;
    g_w2[gb + 1 * C_] = e2 * inv;
    g_w2[gb + 2 * C_] = e3 * inv;
    g_w2[gb + 3 * C_] = e4 * inv;
}

// ---------------- Kernel 3: apply gates (R9-proven, at LTS cap) ----------------
__global__ void k_apply(const float* __restrict__ y,
                        const float* __restrict__ x0,
                        const float* __restrict__ x1,
                        const float* __restrict__ x2,
                        const float* __restrict__ x3,
                        float* __restrict__ out) {
    int blk = gridDim.x - 1 - blockIdx.x;            // reversed
    int t = threadIdx.x;
    int i0 = blk * 512 + t;
    int i1 = i0 + 256;

    const float4* Y  = reinterpret_cast<const float4*>(y);
    const float4* X0 = reinterpret_cast<const float4*>(x0);
    const float4* X1 = reinterpret_cast<const float4*>(x1);
    const float4* X2 = reinterpret_cast<const float4*>(x2);
    const float4* X3 = reinterpret_cast<const float4*>(x3);

    // Gate-independent loads first (overlap with gate kernels via PDL)
    float4 ya = Y[i0],  yb = Y[i1];
    float4 p0 = X0[i0], q0 = X0[i1];
    float4 p1 = X1[i0], q1 = X1[i1];
    float4 p2 = X2[i0], q2 = X2[i1];
    float4 p3 = X3[i0], q3 = X3[i1];

    cudaGridDependencySynchronize();

    int bc0 = blk * 2;
    int bc1 = bc0 + 1;
    int b = bc0 >> 8;
    int c0 = bc0 & 255, c1 = bc1 & 255;
    float w1a = g_w1[bc0],               w1b = g_w1[bc1];
    int ga = b * K_ * C_ + c0,           gb = b * K_ * C_ + c1;
    float a0 = g_w2[ga + 0 * C_], b0 = g_w2[gb + 0 * C_];
    float a1 = g_w2[ga + 1 * C_], b1 = g_w2[gb + 1 * C_];
    float a2 = g_w2[ga + 2 * C_], b2 = g_w2[gb + 2 * C_];
    float a3 = g_w2[ga + 3 * C_], b3 = g_w2[gb + 3 * C_];

    float4 r;
    r.x = fmaf(ya.x, w1a, fmaf(a0, p0.x, fmaf(a1, p1.x, fmaf(a2, p2.x, a3 * p3.x))));
    r.y = fmaf(ya.y, w1a, fmaf(a0, p0.y, fmaf(a1, p1.y, fmaf(a2, p2.y, a3 * p3.y))));
    r.z = fmaf(ya.z, w1a, fmaf(a0, p0.z, fmaf(a1, p1.z, fmaf(a2, p2.z, a3 * p3.z))));
    r.w = fmaf(ya.w, w1a, fmaf(a0, p0.w, fmaf(a1, p1.w, fmaf(a2, p2.w, a3 * p3.w))));
    __stcs(reinterpret_cast<float4*>(out) + i0, r);

    float4 s;
    s.x = fmaf(yb.x, w1b, fmaf(b0, q0.x, fmaf(b1, q1.x, fmaf(b2, q2.x, b3 * q3.x))));
    s.y = fmaf(yb.y, w1b, fmaf(b0, q0.y, fmaf(b1, q1.y, fmaf(b2, q2.y, b3 * q3.y))));
    s.z = fmaf(yb.z, w1b, fmaf(b0, q0.z, fmaf(b1, q1.z, fmaf(b2, q2.z, b3 * q3.z))));
    s.w = fmaf(yb.w, w1b, fmaf(b0, q0.w, fmaf(b1, q1.w, fmaf(b2, q2.w, b3 * q3.w))));
    __stcs(reinterpret_cast<float4*>(out) + i1, s);
}

extern "C" void kernel_launch(void* const* d_in, const int* in_sizes, int n_in,
                              void* d_out, int out_size) {
    const float* y       = (const float*)d_in[0];
    const float* x0      = (const float*)d_in[1];
    const float* x1      = (const float*)d_in[2];
    const float* x2      = (const float*)d_in[3];
    const float* x3      = (const float*)d_in[4];
    const float* conv1_w = (const float*)d_in[5];
    const float* bn_g    = (const float*)d_in[6];
    const float* bn_b    = (const float*)d_in[7];
    const float* bn_m    = (const float*)d_in[8];
    const float* bn_v    = (const float*)d_in[9];
    const float* conv2_w = (const float*)d_in[10];
    const float* conv2_b = (const float*)d_in[11];
    float* out = (float*)d_out;

    // 20480 warps (2 rows each) -> 2560 blocks
    k_means<<<2560, 256>>>(y, x0, x1, x2, x3);

    cudaLaunchAttribute attr[1];
    attr[0].id = cudaLaunchAttributeProgrammaticStreamSerialization;
    attr[0].val.programmaticStreamSerializationAllowed = 1;

    {   cudaLaunchConfig_t cfg = {};
        cfg.gridDim = dim3(32, 1, 1);
        cfg.blockDim = dim3(256, 1, 1);
        cfg.stream = 0; cfg.attrs = attr; cfg.numAttrs = 1;
        cudaLaunchKernelEx(&cfg, k_gate1, conv1_w, bn_g, bn_b, bn_m, bn_v);
    }
    {   cudaLaunchConfig_t cfg = {};
        cfg.gridDim = dim3(32, 1, 1);
        cfg.blockDim = dim3(256, 1, 1);
        cfg.stream = 0; cfg.attrs = attr; cfg.numAttrs = 1;
        cudaLaunchKernelEx(&cfg, k_gate2, conv2_w, conv2_b);
    }
    {   cudaLaunchConfig_t cfg = {};
        cfg.gridDim = dim3(4096, 1, 1);
        cfg.blockDim = dim3(256, 1, 1);
        cfg.stream = 0; cfg.attrs = attr; cfg.numAttrs = 1;
        cudaLaunchKernelEx(&cfg, k_apply, y, x0, x1, x2, x3, out);
    }
}

// round 15
// speedup vs baseline: 1.0433x; 1.0433x over previous
#include <cuda_runtime.h>
#include <math.h>

// Scratch (no cudaMalloc allowed)
__device__ float g_feats[32 * 1280];   // [B, (K+1)*C] pooled means
__device__ float g_h[32 * 32];         // [MID][B] hidden after BN+ReLU (transposed)
__device__ float g_w1[32 * 256];       // [B, C] sigmoid self-gate
__device__ float g_w2[32 * 4 * 256];   // [B, K, C] softmax branch gates

#define B_ 32
#define C_ 256
#define K_ 4
#define HW_ 1024
#define MID_ 32
#define FEAT_ 1280   // (K+1)*C

// ---------------- Kernel 1: global average pool (R9-proven best) ----------------
// One warp per (b, slot, c) row of 1024 contiguous floats. 40960 warps total.
__global__ void k_means(const float* __restrict__ y,
                        const float* __restrict__ x0,
                        const float* __restrict__ x1,
                        const float* __restrict__ x2,
                        const float* __restrict__ x3) {
    int warp = (blockIdx.x * blockDim.x + threadIdx.x) >> 5;
    int lane = threadIdx.x & 31;
    int b = warp / FEAT_;
    int j = warp - b * FEAT_;       // slot*256 + c
    int slot = j >> 8;
    int c = j & 255;
    const float* base;
    switch (slot) {
        case 0: base = y;  break;
        case 1: base = x0; break;
        case 2: base = x1; break;
        case 3: base = x2; break;
        default: base = x3; break;
    }
    const float4* p = reinterpret_cast<const float4*>(base + (size_t)(b * C_ + c) * HW_);
    float s = 0.f;
#pragma unroll
    for (int i = 0; i < 8; i++) {
        float4 v = p[lane + i * 32];
        s += (v.x + v.y) + (v.z + v.w);
    }
#pragma unroll
    for (int o = 16; o; o >>= 1) s += __shfl_xor_sync(0xffffffffu, s, o);
    if (lane == 0) g_feats[warp] = s * (1.0f / 1024.0f);
}

// ---------------- Kernel 2a: GEMM1 + BN + ReLU, weight-coalesced ----------------
// One block per mid channel (32 blocks). Weight row loaded to smem BEFORE the
// grid dependency sync -> weight DRAM latency overlaps k_means' tail.
__global__ void k_gate1(const float* __restrict__ conv1_w,   // [32,1280]
                        const float* __restrict__ bn_gamma,
                        const float* __restrict__ bn_beta,
                        const float* __restrict__ bn_mean,
                        const float* __restrict__ bn_var) {
    cudaTriggerProgrammaticLaunchCompletion();   // let k_gate2 launch now

    int m = blockIdx.x;
    int t = threadIdx.x;
    __shared__ float sw[FEAT_];

    // Gate-independent: weight row + BN scalars (overlap with k_means)
    for (int i = t; i < FEAT_; i += 256) sw[i] = conv1_w[m * FEAT_ + i];
    float mean = bn_mean[m];
    float scale = bn_gamma[m] * rsqrtf(bn_var[m] + 1e-5f);
    float beta = bn_beta[m];

    cudaGridDependencySynchronize();             // wait for g_feats
    __syncthreads();

    int w = t >> 5, lane = t & 31;
    // Each of 8 warps handles 4 batches
#pragma unroll
    for (int bb = 0; bb < 4; bb++) {
        int b = w * 4 + bb;
        const float* f = g_feats + b * FEAT_;
        float s = 0.f;
#pragma unroll
        for (int k = 0; k < FEAT_ / 32; k++)
            s = fmaf(f[lane + k * 32], sw[lane + k * 32], s);
#pragma unroll
        for (int o = 16; o; o >>= 1) s += __shfl_xor_sync(0xffffffffu, s, o);
        if (lane == 0)
            g_h[m * B_ + b] = fmaxf(fmaf(s - mean, scale, beta), 0.f);
    }
}

// ---------------- Kernel 2b: GEMM2 + activations, weight-coalesced ----------------
// One block per group of 8 channels (32 blocks). conv2_w slice + biases loaded
// BEFORE the sync; h loaded after. Thread (b, c_local) computes all 5 slots.
__global__ void k_gate2(const float* __restrict__ conv2_w,   // [1280,32]
                        const float* __restrict__ conv2_b) { // [1280]
    cudaTriggerProgrammaticLaunchCompletion();   // let k_apply launch now

    int cg = blockIdx.x;        // channel group: channels [cg*8, cg*8+8)
    int t = threadIdx.x;        // 256
    int c_local = t & 7;
    int b = t >> 3;

    __shared__ float sh2[5 * 8 * 33];            // [slot][c_local][mid], padded
    __shared__ float shh[MID_ * B_];             // [mid][b]

    // Gate-independent: conv2_w slice (5 x 256 contiguous floats) + biases
#pragma unroll
    for (int slot = 0; slot < 5; slot++) {
        int row = t >> 5, mid = t & 31;          // 8 rows x 32 mids = 256
        sh2[(slot * 8 + row) * 33 + mid] = conv2_w[(slot * 256 + cg * 8) * 32 + t];
    }
    float bias[5];
#pragma unroll
    for (int slot = 0; slot < 5; slot++)
        bias[slot] = conv2_b[slot * 256 + cg * 8 + c_local];

    cudaGridDependencySynchronize();             // wait for g_h
    for (int i = t; i < MID_ * B_; i += 256) shh[i] = g_h[i];
    __syncthreads();

    int c = cg * 8 + c_local;
    float v[5];
#pragma unroll
    for (int slot = 0; slot < 5; slot++) {
        float s = bias[slot];
        const float* wp = &sh2[(slot * 8 + c_local) * 33];
#pragma unroll
        for (int mid = 0; mid < MID_; mid++)
            s = fmaf(shh[mid * B_ + b], wp[mid], s);
        v[slot] = s;
    }

    g_w1[b * C_ + c] = 1.0f / (1.0f + expf(-v[0]));
    float mx = fmaxf(fmaxf(v[1], v[2]), fmaxf(v[3], v[4]));
    float e1 = expf(v[1] - mx), e2 = expf(v[2] - mx);
    float e3 = expf(v[3] - mx), e4 = expf(v[4] - mx);
    float inv = 1.0f / (e1 + e2 + e3 + e4);
    int gb = b * K_ * C_ + c;
    g_w2[gb + 0 * C_] = e1 * inv;
    g_w2[gb + 1 * C_] = e2 * inv;
    g_w2[gb + 2 * C_] = e3 * inv;
    g_w2[gb + 3 * C_] = e4 * inv;
}

// ---------------- Kernel 3: apply gates (2 sweeps/thread, reversed, PDL) -----------
__global__ void k_apply(const float* __restrict__ y,
                        const float* __restrict__ x0,
                        const float* __restrict__ x1,
                        const float* __restrict__ x2,
                        const float* __restrict__ x3,
                        float* __restrict__ out) {
    int blk = gridDim.x - 1 - blockIdx.x;            // reversed
    int t = threadIdx.x;
    int i0 = blk * 512 + t;
    int i1 = i0 + 256;

    const float4* Y  = reinterpret_cast<const float4*>(y);
    const float4* X0 = reinterpret_cast<const float4*>(x0);
    const float4* X1 = reinterpret_cast<const float4*>(x1);
    const float4* X2 = reinterpret_cast<const float4*>(x2);
    const float4* X3 = reinterpret_cast<const float4*>(x3);

    // Gate-independent loads first (overlap with gate kernels via PDL)
    float4 ya = Y[i0],  yb = Y[i1];
    float4 p0 = X0[i0], q0 = X0[i1];
    float4 p1 = X1[i0], q1 = X1[i1];
    float4 p2 = X2[i0], q2 = X2[i1];
    float4 p3 = X3[i0], q3 = X3[i1];

    cudaGridDependencySynchronize();

    int bc0 = blk * 2;
    int bc1 = bc0 + 1;
    int b = bc0 >> 8;
    int c0 = bc0 & 255, c1 = bc1 & 255;
    float w1a = g_w1[bc0],               w1b = g_w1[bc1];
    int ga = b * K_ * C_ + c0,           gb = b * K_ * C_ + c1;
    float a0 = g_w2[ga + 0 * C_], b0 = g_w2[gb + 0 * C_];
    float a1 = g_w2[ga + 1 * C_], b1 = g_w2[gb + 1 * C_];
    float a2 = g_w2[ga + 2 * C_], b2 = g_w2[gb + 2 * C_];
    float a3 = g_w2[ga + 3 * C_], b3 = g_w2[gb + 3 * C_];

    float4 r;
    r.x = fmaf(ya.x, w1a, fmaf(a0, p0.x, fmaf(a1, p1.x, fmaf(a2, p2.x, a3 * p3.x))));
    r.y = fmaf(ya.y, w1a, fmaf(a0, p0.y, fmaf(a1, p1.y, fmaf(a2, p2.y, a3 * p3.y))));
    r.z = fmaf(ya.z, w1a, fmaf(a0, p0.z, fmaf(a1, p1.z, fmaf(a2, p2.z, a3 * p3.z))));
    r.w = fmaf(ya.w, w1a, fmaf(a0, p0.w, fmaf(a1, p1.w, fmaf(a2, p2.w, a3 * p3.w))));
    __stcs(reinterpret_cast<float4*>(out) + i0, r);

    float4 s;
    s.x = fmaf(yb.x, w1b, fmaf(b0, q0.x, fmaf(b1, q1.x, fmaf(b2, q2.x, b3 * q3.x))));
    s.y = fmaf(yb.y, w1b, fmaf(b0, q0.y, fmaf(b1, q1.y, fmaf(b2, q2.y, b3 * q3.y))));
    s.z = fmaf(yb.z, w1b, fmaf(b0, q0.z, fmaf(b1, q1.z, fmaf(b2, q2.z, b3 * q3.z))));
    s.w = fmaf(yb.w, w1b, fmaf(b0, q0.w, fmaf(b1, q1.w, fmaf(b2, q2.w, b3 * q3.w))));
    __stcs(reinterpret_cast<float4*>(out) + i1, s);
}

extern "C" void kernel_launch(void* const* d_in, const int* in_sizes, int n_in,
                              void* d_out, int out_size) {
    const float* y       = (const float*)d_in[0];
    const float* x0      = (const float*)d_in[1];
    const float* x1      = (const float*)d_in[2];
    const float* x2      = (const float*)d_in[3];
    const float* x3      = (const float*)d_in[4];
    const float* conv1_w = (const float*)d_in[5];
    const float* bn_g    = (const float*)d_in[6];
    const float* bn_b    = (const float*)d_in[7];
    const float* bn_m    = (const float*)d_in[8];
    const float* bn_v    = (const float*)d_in[9];
    const float* conv2_w = (const float*)d_in[10];
    const float* conv2_b = (const float*)d_in[11];
    float* out = (float*)d_out;

    k_means<<<5120, 256>>>(y, x0, x1, x2, x3);

    cudaLaunchAttribute attr[1];
    attr[0].id = cudaLaunchAttributeProgrammaticStreamSerialization;
    attr[0].val.programmaticStreamSerializationAllowed = 1;

    {   // GEMM1+BN+ReLU
        cudaLaunchConfig_t cfg = {};
        cfg.gridDim = dim3(32, 1, 1);
        cfg.blockDim = dim3(256, 1, 1);
        cfg.stream = 0;
        cfg.attrs = attr;
        cfg.numAttrs = 1;
        cudaLaunchKernelEx(&cfg, k_gate1, conv1_w, bn_g, bn_b, bn_m, bn_v);
    }
    {   // GEMM2+activations
        cudaLaunchConfig_t cfg = {};
        cfg.gridDim = dim3(32, 1, 1);
        cfg.blockDim = dim3(256, 1, 1);
        cfg.stream = 0;
        cfg.attrs = attr;
        cfg.numAttrs = 1;
        cudaLaunchKernelEx(&cfg, k_gate2, conv2_w, conv2_b);
    }
    {   // apply
        cudaLaunchConfig_t cfg = {};
        cfg.gridDim = dim3(4096, 1, 1);
        cfg.blockDim = dim3(256, 1, 1);
        cfg.stream = 0;
        cfg.attrs = attr;
        cfg.numAttrs = 1;
        cudaLaunchKernelEx(&cfg, k_apply, y, x0, x1, x2, x3, out);
    }
}